// round 10
// baseline (speedup 1.0000x reference)
#include <cuda_runtime.h>

// SpatialTransformer3D: B=4, vol 128^3, C=2, resampled 128^3.
// R10 = R9 body + amortization: 128-thread blocks, 8 points/thread.
// Each warp owns 32(i1 lanes) x 8(i2 chain) of the 32x32 tile, processed as
// four 2-step batches (16 loads in flight each). Per-thread fixed costs
// (12 param loads, coord setup, decode) amortize over 8 points instead of 4.

#define R3_ (128*128*128)

__device__ __forceinline__ int clampi(int v, int lo, int hi) {
    return v < lo ? lo : (v > hi ? hi : v);
}

struct Pt {
    unsigned xb0, xb1;                   // x corner byte offsets (x<<3)
    unsigned rb00, rb01, rb10, rb11;     // row byte offsets (z<<17)+(y<<10)
    float x, y, z;
    int x0, x1, y0, y1, z0, z1;
};

__device__ __forceinline__ Pt make_pt(float x, float y, float z) {
    Pt p;
    int xi = (int)x, yi = (int)y, zi = (int)z;   // trunc toward zero (astype)
    p.x0 = clampi(xi,     0, 127);
    p.x1 = clampi(xi + 1, 0, 127);
    p.y0 = clampi(yi,     0, 127);
    p.y1 = clampi(yi + 1, 0, 127);
    p.z0 = clampi(zi,     0, 127);
    p.z1 = clampi(zi + 1, 0, 127);
    unsigned iz0 = (unsigned)p.z0 << 17, iz1 = (unsigned)p.z1 << 17;
    unsigned iy0 = (unsigned)p.y0 << 10, iy1 = (unsigned)p.y1 << 10;
    p.rb00 = iz0 + iy0;  p.rb01 = iz0 + iy1;
    p.rb10 = iz1 + iy0;  p.rb11 = iz1 + iy1;
    p.xb0 = (unsigned)p.x0 << 3;
    p.xb1 = (unsigned)p.x1 << 3;
    p.x = x; p.y = y; p.z = z;
    return p;
}

__device__ __forceinline__ float2 ld2(const char* base, unsigned off) {
    return __ldg((const float2*)(base + off));
}

// weights computed after load issuance, then weighted sum (reference order)
__device__ __forceinline__ float2 lerp8(const Pt& p,
    float2 v000, float2 v001, float2 v010, float2 v011,
    float2 v100, float2 v101, float2 v110, float2 v111)
{
    float wx0 = (float)p.x1 - p.x, wx1 = p.x - (float)p.x0;
    float wy0 = (float)p.y1 - p.y, wy1 = p.y - (float)p.y0;
    float wz0 = (float)p.z1 - p.z, wz1 = p.z - (float)p.z0;

    float wxy00 = wx0 * wy0;
    float wxy01 = wx0 * wy1;
    float wxy10 = wx1 * wy0;
    float wxy11 = wx1 * wy1;
    float w000 = wxy00 * wz0, w100 = wxy00 * wz1;
    float w010 = wxy01 * wz0, w110 = wxy01 * wz1;
    float w001 = wxy10 * wz0, w101 = wxy10 * wz1;
    float w011 = wxy11 * wz0, w111 = wxy11 * wz1;

    float2 acc;
    acc.x = w000 * v000.x;                 acc.y = w000 * v000.y;
    acc.x = fmaf(w100, v100.x, acc.x);     acc.y = fmaf(w100, v100.y, acc.y);
    acc.x = fmaf(w010, v010.x, acc.x);     acc.y = fmaf(w010, v010.y, acc.y);
    acc.x = fmaf(w110, v110.x, acc.x);     acc.y = fmaf(w110, v110.y, acc.y);
    acc.x = fmaf(w001, v001.x, acc.x);     acc.y = fmaf(w001, v001.y, acc.y);
    acc.x = fmaf(w101, v101.x, acc.x);     acc.y = fmaf(w101, v101.y, acc.y);
    acc.x = fmaf(w011, v011.x, acc.x);     acc.y = fmaf(w011, v011.y, acc.y);
    acc.x = fmaf(w111, v111.x, acc.x);     acc.y = fmaf(w111, v111.y, acc.y);
    return acc;
}

__global__ __launch_bounds__(128, 8)
void st3d_kernel(const float* __restrict__ images,
                 const float* __restrict__ params,
                 float2* __restrict__ out)
{
    __shared__ float2 tile[32][33];

    int lane = threadIdx.x & 31;
    int warp = threadIdx.x >> 5;    // 0..3, owns i2 chain [8w, 8w+8)

    int i2t = (blockIdx.x & 3) << 5;
    int i1t = (blockIdx.x >> 2) << 5;
    int i0  = blockIdx.y;
    int b   = blockIdx.z;

    const float* m = params + b * 12;
    float m00 = __ldg(m+0),  m01 = __ldg(m+1),  m02 = __ldg(m+2),  m03 = __ldg(m+3);
    float m10 = __ldg(m+4),  m11 = __ldg(m+5),  m12 = __ldg(m+6),  m13 = __ldg(m+7);
    float m20 = __ldg(m+8),  m21 = __ldg(m+9),  m22 = __ldg(m+10), m23 = __ldg(m+11);

    const float step = 2.0f / 127.0f;
    int i1 = i1t + lane;
    float xn = fmaf((float)i1, step, -1.0f);
    float yn = fmaf((float)i0, step, -1.0f);

    // coord(fi2) = d * fi2 + c
    float gx = fmaf(m00, xn, fmaf(m01, yn, m03));
    float gy = fmaf(m10, xn, fmaf(m11, yn, m13));
    float gz = fmaf(m20, xn, fmaf(m21, yn, m23));
    float dxz = 64.0f * step * m02;
    float dyz = 64.0f * step * m12;
    float dzz = 64.0f * step * m22;
    float cx = (gx - m02 + 1.0f) * 64.0f;
    float cy = (gy - m12 + 1.0f) * 64.0f;
    float cz = (gz - m22 + 1.0f) * 64.0f;

    const char* __restrict__ vol =
        (const char*)images + ((size_t)b * R3_ * 8);

    float fbase = (float)(i2t + (warp << 3));

    #pragma unroll
    for (int jj = 0; jj < 4; jj++) {
        float fA = fbase + (float)(jj * 2);
        float fB = fA + 1.0f;

        Pt A = make_pt(fmaf(dxz, fA, cx), fmaf(dyz, fA, cy), fmaf(dzz, fA, cz));
        Pt B = make_pt(fmaf(dxz, fB, cx), fmaf(dyz, fB, cy), fmaf(dzz, fB, cz));

        // all 16 gathers issued before any weight math / consumption
        float2 a000 = ld2(vol, A.rb00 + A.xb0);
        float2 a100 = ld2(vol, A.rb10 + A.xb0);
        float2 a010 = ld2(vol, A.rb01 + A.xb0);
        float2 a110 = ld2(vol, A.rb11 + A.xb0);
        float2 a001 = ld2(vol, A.rb00 + A.xb1);
        float2 a101 = ld2(vol, A.rb10 + A.xb1);
        float2 a011 = ld2(vol, A.rb01 + A.xb1);
        float2 a111 = ld2(vol, A.rb11 + A.xb1);

        float2 b000 = ld2(vol, B.rb00 + B.xb0);
        float2 b100 = ld2(vol, B.rb10 + B.xb0);
        float2 b010 = ld2(vol, B.rb01 + B.xb0);
        float2 b110 = ld2(vol, B.rb11 + B.xb0);
        float2 b001 = ld2(vol, B.rb00 + B.xb1);
        float2 b101 = ld2(vol, B.rb10 + B.xb1);
        float2 b011 = ld2(vol, B.rb01 + B.xb1);
        float2 b111 = ld2(vol, B.rb11 + B.xb1);

        int rowA = (warp << 3) + jj * 2;
        tile[rowA][lane] =
            lerp8(A, a000, a001, a010, a011, a100, a101, a110, a111);
        tile[rowA + 1][lane] =
            lerp8(B, b000, b001, b010, b011, b100, b101, b110, b111);
    }

    __syncthreads();

    size_t out_base = (((size_t)b << 7) + i0) << 14;
    #pragma unroll
    for (int j = 0; j < 8; j++) {
        int i1l = warp + (j << 2);
        float2 v = tile[lane][i1l];
        out[out_base + (size_t)(i1t + i1l) * 128 + (i2t + lane)] = v;
    }
}

extern "C" void kernel_launch(void* const* d_in, const int* in_sizes, int n_in,
                              void* d_out, int out_size)
{
    const float* images = (const float*)d_in[0];
    const float* params = (const float*)d_in[1];
    float2* out = (float2*)d_out;

    dim3 grid(16, 128, 4);   // (i2t,i1t) x i0 x b
    st3d_kernel<<<grid, 128>>>(images, params, out);
}

// round 11
// speedup vs baseline: 1.4172x; 1.4172x over previous
#include <cuda_runtime.h>

// SpatialTransformer3D: B=4, vol 128^3, C=2, resampled 128^3.
// R11 = R9 champion + vectorized param loads (3x LDG.128).
// Tile 32(i1) x 32(i2); lanes along i1 (coalesced gathers), merged float2
// smem tile transpose, coalesced i2 stores. 256 threads, 4 points/thread,
// 2 i2-steps batched (16 loads in flight), 32-bit [UR+R] addressing,
// weights deferred past load issuance.

#define R3_ (128*128*128)

__device__ __forceinline__ int clampi(int v, int lo, int hi) {
    return v < lo ? lo : (v > hi ? hi : v);
}

struct Pt {
    unsigned xb0, xb1;                   // x corner byte offsets (x<<3)
    unsigned rb00, rb01, rb10, rb11;     // row byte offsets (z<<17)+(y<<10)
    float x, y, z;
    int x0, x1, y0, y1, z0, z1;
};

__device__ __forceinline__ Pt make_pt(float x, float y, float z) {
    Pt p;
    int xi = (int)x, yi = (int)y, zi = (int)z;   // trunc toward zero (astype)
    p.x0 = clampi(xi,     0, 127);
    p.x1 = clampi(xi + 1, 0, 127);
    p.y0 = clampi(yi,     0, 127);
    p.y1 = clampi(yi + 1, 0, 127);
    p.z0 = clampi(zi,     0, 127);
    p.z1 = clampi(zi + 1, 0, 127);
    unsigned iz0 = (unsigned)p.z0 << 17, iz1 = (unsigned)p.z1 << 17;
    unsigned iy0 = (unsigned)p.y0 << 10, iy1 = (unsigned)p.y1 << 10;
    p.rb00 = iz0 + iy0;  p.rb01 = iz0 + iy1;
    p.rb10 = iz1 + iy0;  p.rb11 = iz1 + iy1;
    p.xb0 = (unsigned)p.x0 << 3;
    p.xb1 = (unsigned)p.x1 << 3;
    p.x = x; p.y = y; p.z = z;
    return p;
}

__device__ __forceinline__ float2 ld2(const char* base, unsigned off) {
    return __ldg((const float2*)(base + off));
}

// weights computed after load issuance, then weighted sum (reference order)
__device__ __forceinline__ float2 lerp8(const Pt& p,
    float2 v000, float2 v001, float2 v010, float2 v011,
    float2 v100, float2 v101, float2 v110, float2 v111)
{
    float wx0 = (float)p.x1 - p.x, wx1 = p.x - (float)p.x0;
    float wy0 = (float)p.y1 - p.y, wy1 = p.y - (float)p.y0;
    float wz0 = (float)p.z1 - p.z, wz1 = p.z - (float)p.z0;

    float wxy00 = wx0 * wy0;
    float wxy01 = wx0 * wy1;
    float wxy10 = wx1 * wy0;
    float wxy11 = wx1 * wy1;
    float w000 = wxy00 * wz0, w100 = wxy00 * wz1;
    float w010 = wxy01 * wz0, w110 = wxy01 * wz1;
    float w001 = wxy10 * wz0, w101 = wxy10 * wz1;
    float w011 = wxy11 * wz0, w111 = wxy11 * wz1;

    float2 acc;
    acc.x = w000 * v000.x;                 acc.y = w000 * v000.y;
    acc.x = fmaf(w100, v100.x, acc.x);     acc.y = fmaf(w100, v100.y, acc.y);
    acc.x = fmaf(w010, v010.x, acc.x);     acc.y = fmaf(w010, v010.y, acc.y);
    acc.x = fmaf(w110, v110.x, acc.x);     acc.y = fmaf(w110, v110.y, acc.y);
    acc.x = fmaf(w001, v001.x, acc.x);     acc.y = fmaf(w001, v001.y, acc.y);
    acc.x = fmaf(w101, v101.x, acc.x);     acc.y = fmaf(w101, v101.y, acc.y);
    acc.x = fmaf(w011, v011.x, acc.x);     acc.y = fmaf(w011, v011.y, acc.y);
    acc.x = fmaf(w111, v111.x, acc.x);     acc.y = fmaf(w111, v111.y, acc.y);
    return acc;
}

__global__ __launch_bounds__(256, 4)
void st3d_kernel(const float* __restrict__ images,
                 const float* __restrict__ params,
                 float2* __restrict__ out)
{
    __shared__ float2 tile[32][33];

    int lane = threadIdx.x & 31;
    int warp = threadIdx.x >> 5;

    int i2t = (blockIdx.x & 3) << 5;
    int i1t = (blockIdx.x >> 2) << 5;
    int i0  = blockIdx.y;
    int b   = blockIdx.z;

    // params row (12 floats, 48B offset per b -> 16B aligned): 3x LDG.128
    const float4* m4 = (const float4*)(params + b * 12);
    float4 p0 = __ldg(m4 + 0);
    float4 p1 = __ldg(m4 + 1);
    float4 p2 = __ldg(m4 + 2);
    float m00 = p0.x, m01 = p0.y, m02 = p0.z, m03 = p0.w;
    float m10 = p1.x, m11 = p1.y, m12 = p1.z, m13 = p1.w;
    float m20 = p2.x, m21 = p2.y, m22 = p2.z, m23 = p2.w;

    const float step = 2.0f / 127.0f;
    int i1 = i1t + lane;
    float xn = fmaf((float)i1, step, -1.0f);
    float yn = fmaf((float)i0, step, -1.0f);

    // coord(fi2) = d * fi2 + c
    float gx = fmaf(m00, xn, fmaf(m01, yn, m03));
    float gy = fmaf(m10, xn, fmaf(m11, yn, m13));
    float gz = fmaf(m20, xn, fmaf(m21, yn, m23));
    float dxz = 64.0f * step * m02;
    float dyz = 64.0f * step * m12;
    float dzz = 64.0f * step * m22;
    float cx = (gx - m02 + 1.0f) * 64.0f;
    float cy = (gy - m12 + 1.0f) * 64.0f;
    float cz = (gz - m22 + 1.0f) * 64.0f;

    const char* __restrict__ vol =
        (const char*)images + ((size_t)b * R3_ * 8);

    float fbase = (float)(i2t + (warp << 2));

    #pragma unroll
    for (int jj = 0; jj < 2; jj++) {
        float fA = fbase + (float)(jj * 2);
        float fB = fA + 1.0f;

        Pt A = make_pt(fmaf(dxz, fA, cx), fmaf(dyz, fA, cy), fmaf(dzz, fA, cz));
        Pt B = make_pt(fmaf(dxz, fB, cx), fmaf(dyz, fB, cy), fmaf(dzz, fB, cz));

        // all 16 gathers issued before any weight math / consumption
        float2 a000 = ld2(vol, A.rb00 + A.xb0);
        float2 a100 = ld2(vol, A.rb10 + A.xb0);
        float2 a010 = ld2(vol, A.rb01 + A.xb0);
        float2 a110 = ld2(vol, A.rb11 + A.xb0);
        float2 a001 = ld2(vol, A.rb00 + A.xb1);
        float2 a101 = ld2(vol, A.rb10 + A.xb1);
        float2 a011 = ld2(vol, A.rb01 + A.xb1);
        float2 a111 = ld2(vol, A.rb11 + A.xb1);

        float2 b000 = ld2(vol, B.rb00 + B.xb0);
        float2 b100 = ld2(vol, B.rb10 + B.xb0);
        float2 b010 = ld2(vol, B.rb01 + B.xb0);
        float2 b110 = ld2(vol, B.rb11 + B.xb0);
        float2 b001 = ld2(vol, B.rb00 + B.xb1);
        float2 b101 = ld2(vol, B.rb10 + B.xb1);
        float2 b011 = ld2(vol, B.rb01 + B.xb1);
        float2 b111 = ld2(vol, B.rb11 + B.xb1);

        int rowA = (warp << 2) + jj * 2;
        tile[rowA][lane] =
            lerp8(A, a000, a001, a010, a011, a100, a101, a110, a111);
        tile[rowA + 1][lane] =
            lerp8(B, b000, b001, b010, b011, b100, b101, b110, b111);
    }

    __syncthreads();

    size_t out_base = (((size_t)b << 7) + i0) << 14;
    #pragma unroll
    for (int j = 0; j < 4; j++) {
        int i1l = warp + (j << 3);
        float2 v = tile[lane][i1l];
        out[out_base + (size_t)(i1t + i1l) * 128 + (i2t + lane)] = v;
    }
}

extern "C" void kernel_launch(void* const* d_in, const int* in_sizes, int n_in,
                              void* d_out, int out_size)
{
    const float* images = (const float*)d_in[0];
    const float* params = (const float*)d_in[1];
    float2* out = (float2*)d_out;

    dim3 grid(16, 128, 4);   // (i2t,i1t) x i0 x b
    st3d_kernel<<<grid, 256>>>(images, params, out);
}

// round 12
// speedup vs baseline: 1.4561x; 1.0274x over previous
#include <cuda_runtime.h>

// SpatialTransformer3D: B=4, vol 128^3, C=2, resampled 128^3.
// R12 = R11 champion with __launch_bounds__(256, 5): target <=51 regs so
// 5 blocks/SM fit (40 warps, +25% latency hiding). Body unchanged:
// 32(i1) x 32(i2) tile, lanes along i1 (coalesced gathers), merged float2
// smem transpose, 16 loads in flight, 32-bit [UR+R] addressing, weights
// deferred past load issuance, 3x LDG.128 param loads.

#define R3_ (128*128*128)

__device__ __forceinline__ int clampi(int v, int lo, int hi) {
    return v < lo ? lo : (v > hi ? hi : v);
}

struct Pt {
    unsigned xb0, xb1;                   // x corner byte offsets (x<<3)
    unsigned rb00, rb01, rb10, rb11;     // row byte offsets (z<<17)+(y<<10)
    float x, y, z;
    int x0, x1, y0, y1, z0, z1;
};

__device__ __forceinline__ Pt make_pt(float x, float y, float z) {
    Pt p;
    int xi = (int)x, yi = (int)y, zi = (int)z;   // trunc toward zero (astype)
    p.x0 = clampi(xi,     0, 127);
    p.x1 = clampi(xi + 1, 0, 127);
    p.y0 = clampi(yi,     0, 127);
    p.y1 = clampi(yi + 1, 0, 127);
    p.z0 = clampi(zi,     0, 127);
    p.z1 = clampi(zi + 1, 0, 127);
    unsigned iz0 = (unsigned)p.z0 << 17, iz1 = (unsigned)p.z1 << 17;
    unsigned iy0 = (unsigned)p.y0 << 10, iy1 = (unsigned)p.y1 << 10;
    p.rb00 = iz0 + iy0;  p.rb01 = iz0 + iy1;
    p.rb10 = iz1 + iy0;  p.rb11 = iz1 + iy1;
    p.xb0 = (unsigned)p.x0 << 3;
    p.xb1 = (unsigned)p.x1 << 3;
    p.x = x; p.y = y; p.z = z;
    return p;
}

__device__ __forceinline__ float2 ld2(const char* base, unsigned off) {
    return __ldg((const float2*)(base + off));
}

// weights computed after load issuance, then weighted sum (reference order)
__device__ __forceinline__ float2 lerp8(const Pt& p,
    float2 v000, float2 v001, float2 v010, float2 v011,
    float2 v100, float2 v101, float2 v110, float2 v111)
{
    float wx0 = (float)p.x1 - p.x, wx1 = p.x - (float)p.x0;
    float wy0 = (float)p.y1 - p.y, wy1 = p.y - (float)p.y0;
    float wz0 = (float)p.z1 - p.z, wz1 = p.z - (float)p.z0;

    float wxy00 = wx0 * wy0;
    float wxy01 = wx0 * wy1;
    float wxy10 = wx1 * wy0;
    float wxy11 = wx1 * wy1;
    float w000 = wxy00 * wz0, w100 = wxy00 * wz1;
    float w010 = wxy01 * wz0, w110 = wxy01 * wz1;
    float w001 = wxy10 * wz0, w101 = wxy10 * wz1;
    float w011 = wxy11 * wz0, w111 = wxy11 * wz1;

    float2 acc;
    acc.x = w000 * v000.x;                 acc.y = w000 * v000.y;
    acc.x = fmaf(w100, v100.x, acc.x);     acc.y = fmaf(w100, v100.y, acc.y);
    acc.x = fmaf(w010, v010.x, acc.x);     acc.y = fmaf(w010, v010.y, acc.y);
    acc.x = fmaf(w110, v110.x, acc.x);     acc.y = fmaf(w110, v110.y, acc.y);
    acc.x = fmaf(w001, v001.x, acc.x);     acc.y = fmaf(w001, v001.y, acc.y);
    acc.x = fmaf(w101, v101.x, acc.x);     acc.y = fmaf(w101, v101.y, acc.y);
    acc.x = fmaf(w011, v011.x, acc.x);     acc.y = fmaf(w011, v011.y, acc.y);
    acc.x = fmaf(w111, v111.x, acc.x);     acc.y = fmaf(w111, v111.y, acc.y);
    return acc;
}

__global__ __launch_bounds__(256, 5)
void st3d_kernel(const float* __restrict__ images,
                 const float* __restrict__ params,
                 float2* __restrict__ out)
{
    __shared__ float2 tile[32][33];

    int lane = threadIdx.x & 31;
    int warp = threadIdx.x >> 5;

    int i2t = (blockIdx.x & 3) << 5;
    int i1t = (blockIdx.x >> 2) << 5;
    int i0  = blockIdx.y;
    int b   = blockIdx.z;

    // params row (12 floats, 48B offset per b -> 16B aligned): 3x LDG.128
    const float4* m4 = (const float4*)(params + b * 12);
    float4 p0 = __ldg(m4 + 0);
    float4 p1 = __ldg(m4 + 1);
    float4 p2 = __ldg(m4 + 2);
    float m00 = p0.x, m01 = p0.y, m02 = p0.z, m03 = p0.w;
    float m10 = p1.x, m11 = p1.y, m12 = p1.z, m13 = p1.w;
    float m20 = p2.x, m21 = p2.y, m22 = p2.z, m23 = p2.w;

    const float step = 2.0f / 127.0f;
    int i1 = i1t + lane;
    float xn = fmaf((float)i1, step, -1.0f);
    float yn = fmaf((float)i0, step, -1.0f);

    // coord(fi2) = d * fi2 + c
    float gx = fmaf(m00, xn, fmaf(m01, yn, m03));
    float gy = fmaf(m10, xn, fmaf(m11, yn, m13));
    float gz = fmaf(m20, xn, fmaf(m21, yn, m23));
    float dxz = 64.0f * step * m02;
    float dyz = 64.0f * step * m12;
    float dzz = 64.0f * step * m22;
    float cx = (gx - m02 + 1.0f) * 64.0f;
    float cy = (gy - m12 + 1.0f) * 64.0f;
    float cz = (gz - m22 + 1.0f) * 64.0f;

    const char* __restrict__ vol =
        (const char*)images + ((size_t)b * R3_ * 8);

    float fbase = (float)(i2t + (warp << 2));

    #pragma unroll
    for (int jj = 0; jj < 2; jj++) {
        float fA = fbase + (float)(jj * 2);
        float fB = fA + 1.0f;

        Pt A = make_pt(fmaf(dxz, fA, cx), fmaf(dyz, fA, cy), fmaf(dzz, fA, cz));
        Pt B = make_pt(fmaf(dxz, fB, cx), fmaf(dyz, fB, cy), fmaf(dzz, fB, cz));

        // all 16 gathers issued before any weight math / consumption
        float2 a000 = ld2(vol, A.rb00 + A.xb0);
        float2 a100 = ld2(vol, A.rb10 + A.xb0);
        float2 a010 = ld2(vol, A.rb01 + A.xb0);
        float2 a110 = ld2(vol, A.rb11 + A.xb0);
        float2 a001 = ld2(vol, A.rb00 + A.xb1);
        float2 a101 = ld2(vol, A.rb10 + A.xb1);
        float2 a011 = ld2(vol, A.rb01 + A.xb1);
        float2 a111 = ld2(vol, A.rb11 + A.xb1);

        float2 b000 = ld2(vol, B.rb00 + B.xb0);
        float2 b100 = ld2(vol, B.rb10 + B.xb0);
        float2 b010 = ld2(vol, B.rb01 + B.xb0);
        float2 b110 = ld2(vol, B.rb11 + B.xb0);
        float2 b001 = ld2(vol, B.rb00 + B.xb1);
        float2 b101 = ld2(vol, B.rb10 + B.xb1);
        float2 b011 = ld2(vol, B.rb01 + B.xb1);
        float2 b111 = ld2(vol, B.rb11 + B.xb1);

        int rowA = (warp << 2) + jj * 2;
        tile[rowA][lane] =
            lerp8(A, a000, a001, a010, a011, a100, a101, a110, a111);
        tile[rowA + 1][lane] =
            lerp8(B, b000, b001, b010, b011, b100, b101, b110, b111);
    }

    __syncthreads();

    size_t out_base = (((size_t)b << 7) + i0) << 14;
    #pragma unroll
    for (int j = 0; j < 4; j++) {
        int i1l = warp + (j << 3);
        float2 v = tile[lane][i1l];
        out[out_base + (size_t)(i1t + i1l) * 128 + (i2t + lane)] = v;
    }
}

extern "C" void kernel_launch(void* const* d_in, const int* in_sizes, int n_in,
                              void* d_out, int out_size)
{
    const float* images = (const float*)d_in[0];
    const float* params = (const float*)d_in[1];
    float2* out = (float2*)d_out;

    dim3 grid(16, 128, 4);   // (i2t,i1t) x i0 x b
    st3d_kernel<<<grid, 256>>>(images, params, out);
}